// round 8
// baseline (speedup 1.0000x reference)
#include <cuda_runtime.h>
#include <cuda_bf16.h>
#include <cstdint>

#define N 4096
#define D 512
#define NN ((size_t)N * (size_t)N)
#define OUT_P 1
#define OUT_C (1 + 16777216)
#define RPB 16            // rows per block in fused rowcol kernel
#define NBLK (N / RPB)    // 256 blocks
#define DSMEM (RPB * N * 2 + N * 4 + 64)   // K tile + v + u = 147520 B

// ---- device scratch (no allocations allowed) ----
__device__ __align__(16) __nv_bfloat16 g_Kb[NN];           // 32 MB bf16 Gibbs kernel
__device__ __align__(16) __nv_bfloat16 g_Sb[(size_t)N * D];
__device__ __align__(16) __nv_bfloat16 g_Tb[(size_t)N * D];
__device__ __align__(16) float g_zp[(size_t)NBLK * N];     // col-sum partials (4 MB)
__device__ __align__(16) float g_sn[N], g_tn[N];
__device__ __align__(16) float g_u[N], g_v[N];
__device__ __align__(16) float g_part[N];

// ---- L2 evict_last via cache-hint policy ----
__device__ __forceinline__ uint64_t evict_last_policy() {
    uint64_t pol;
    asm("createpolicy.fractional.L2::evict_last.b64 %0, 1.0;" : "=l"(pol));
    return pol;
}
__device__ __forceinline__ uint4 ldK16(const __nv_bfloat16* p, uint64_t pol) {
    uint4 r;
    asm volatile("ld.global.nc.L2::cache_hint.v4.u32 {%0,%1,%2,%3}, [%4], %5;"
                 : "=r"(r.x), "=r"(r.y), "=r"(r.z), "=r"(r.w)
                 : "l"(p), "l"(pol));
    return r;
}
__device__ __forceinline__ void stK4(__nv_bfloat16* p, uint32_t v, uint64_t pol) {
    asm volatile("st.global.L2::cache_hint.u32 [%0], %1, %2;"
                 :: "l"(p), "r"(v), "l"(pol));
}

// bf16 m16n8k16 mma, fp32 accumulate
__device__ __forceinline__ void mma16(float* c, const uint32_t* a,
                                      uint32_t b0, uint32_t b1) {
    asm volatile(
        "mma.sync.aligned.m16n8k16.row.col.f32.bf16.bf16.f32 "
        "{%0,%1,%2,%3},{%4,%5,%6,%7},{%8,%9},{%0,%1,%2,%3};"
        : "+f"(c[0]), "+f"(c[1]), "+f"(c[2]), "+f"(c[3])
        : "r"(a[0]), "r"(a[1]), "r"(a[2]), "r"(a[3]), "r"(b0), "r"(b1));
}
__device__ __forceinline__ void ldsm4(uint32_t* r, uint32_t addr) {
    asm volatile("ldmatrix.sync.aligned.m8n8.x4.shared.b16 {%0,%1,%2,%3}, [%4];"
                 : "=r"(r[0]), "=r"(r[1]), "=r"(r[2]), "=r"(r[3]) : "r"(addr));
}

// ---- init: v0 = 1 ----
__global__ void init_kernel() {
    int i = blockIdx.x * blockDim.x + threadIdx.x;
    if (i < N) g_v[i] = 1.0f;
}

// ---- fused convert fp32->bf16 + row sq-norms; one block = 2 rows ----
__global__ void cvt_norm_kernel(const float* __restrict__ X, __nv_bfloat16* __restrict__ Y,
                                float* __restrict__ nrm) {
    __shared__ float ws[8];
    int tid = threadIdx.x;
    size_t base = (size_t)blockIdx.x * 1024 + tid * 4;
    float4 a = *(const float4*)(X + base);
    uint2 o;
    __nv_bfloat162 lo = __floats2bfloat162_rn(a.x, a.y);
    __nv_bfloat162 hi = __floats2bfloat162_rn(a.z, a.w);
    o.x = *(uint32_t*)&lo;
    o.y = *(uint32_t*)&hi;
    *(uint2*)(Y + base) = o;
    float s = a.x * a.x + a.y * a.y + a.z * a.z + a.w * a.w;
#pragma unroll
    for (int of = 16; of > 0; of >>= 1) s += __shfl_xor_sync(0xffffffffu, s, of);
    if ((tid & 31) == 0) ws[tid >> 5] = s;
    __syncthreads();
    if (tid == 0)   nrm[blockIdx.x * 2]     = ws[0] + ws[1] + ws[2] + ws[3];
    if (tid == 128) nrm[blockIdx.x * 2 + 1] = ws[4] + ws[5] + ws[6] + ws[7];
}

// ---- bf16 tensor-core GEMM, cp.async double-buffered, ldmatrix operands ----
__global__ void __launch_bounds__(256) gemm_kernel(float* __restrict__ out) {
    __shared__ __align__(16) char As[2][128 * 80];
    __shared__ __align__(16) char Bs[2][128 * 80];
    const int tid  = threadIdx.x;
    const int lane = tid & 31, warp = tid >> 5;
    const int wm = warp & 1, wn = warp >> 1;
    const int bi = blockIdx.y, bj = blockIdx.x;

    // ldmatrix lane->row/k mapping (x4: tiles = (r0-7,klo),(r8-15,klo),(r0-7,khi),(r8-15,khi))
    const int laneRow = (lane & 7) + ((lane >> 3) & 1) * 8;
    const int laneK   = (lane >> 4) * 16;

    float acc[4][4][4];
#pragma unroll
    for (int a = 0; a < 4; a++)
#pragma unroll
        for (int b = 0; b < 4; b++)
#pragma unroll
            for (int r = 0; r < 4; r++) acc[a][b][r] = 0.f;

    const __nv_bfloat16* Sb = g_Sb + (size_t)bi * 128 * D;
    const __nv_bfloat16* Tb = g_Tb + (size_t)bj * 128 * D;

    auto load_chunk = [&](int kc, int buf) {
#pragma unroll
        for (int q = 0; q < 2; q++) {
            int f = tid + 256 * q;
            int r = f >> 2, seg = f & 3;
            const __nv_bfloat16* sa = Sb + (size_t)r * D + kc + seg * 8;
            const __nv_bfloat16* sb = Tb + (size_t)r * D + kc + seg * 8;
            uint32_t da = (uint32_t)__cvta_generic_to_shared(&As[buf][r * 80 + seg * 16]);
            uint32_t db = (uint32_t)__cvta_generic_to_shared(&Bs[buf][r * 80 + seg * 16]);
            asm volatile("cp.async.cg.shared.global [%0], [%1], 16;\n\t"
                         "cp.async.cg.shared.global [%2], [%3], 16;"
                         :: "r"(da), "l"(sa), "r"(db), "l"(sb));
        }
        asm volatile("cp.async.commit_group;");
    };

    load_chunk(0, 0);
    for (int c = 0; c < 16; c++) {
        if (c + 1 < 16) {
            load_chunk((c + 1) * 32, (c + 1) & 1);
            asm volatile("cp.async.wait_group 1;");
        } else {
            asm volatile("cp.async.wait_group 0;");
        }
        __syncthreads();
        uint32_t aBase = (uint32_t)__cvta_generic_to_shared(
            &As[c & 1][(wm * 64 + laneRow) * 80 + laneK]);
        uint32_t bBase = (uint32_t)__cvta_generic_to_shared(
            &Bs[c & 1][(wn * 32 + laneRow) * 80 + laneK]);
#pragma unroll
        for (int s = 0; s < 2; s++) {
            uint32_t aF[4][4], bF[2][4];
#pragma unroll
            for (int mi = 0; mi < 4; mi++) ldsm4(aF[mi], aBase + mi * 16 * 80 + s * 32);
#pragma unroll
            for (int nh = 0; nh < 2; nh++) ldsm4(bF[nh], bBase + nh * 16 * 80 + s * 32);
#pragma unroll
            for (int mi = 0; mi < 4; mi++)
#pragma unroll
                for (int ni = 0; ni < 4; ni++)
                    mma16(acc[mi][ni], aF[mi],
                          bF[ni >> 1][ni & 1], bF[ni >> 1][2 + (ni & 1)]);
        }
        __syncthreads();
    }

    uint64_t pol = evict_last_policy();
    float* outC = out + OUT_C;
    const int quad = lane >> 2;
#pragma unroll
    for (int mi = 0; mi < 4; mi++) {
#pragma unroll
        for (int ni = 0; ni < 4; ni++) {
            int row0 = bi * 128 + wm * 64 + mi * 16 + quad;
            int col  = bj * 128 + wn * 32 + ni * 8 + (lane & 3) * 2;
#pragma unroll
            for (int h = 0; h < 2; h++) {
                int rr = row0 + h * 8;
                float d0 = acc[mi][ni][2 * h], d1 = acc[mi][ni][2 * h + 1];
                float sn = g_sn[rr];
                float c0 = sqrtf(fmaxf(sn + g_tn[col]     - 2.f * d0, 0.f));
                float c1 = sqrtf(fmaxf(sn + g_tn[col + 1] - 2.f * d1, 0.f));
                __stcs(&outC[(size_t)rr * N + col],     c0);
                __stcs(&outC[(size_t)rr * N + col + 1], c1);
                __nv_bfloat162 kk = __floats2bfloat162_rn(__expf(-0.125f * c0),
                                                          __expf(-0.125f * c1));
                stK4(&g_Kb[(size_t)rr * N + col], *(uint32_t*)&kk, pol);
            }
        }
    }
}

// ---- FUSED Sinkhorn half-iteration: block = 16 rows of K ----
// Phase 1: one warp per row -> row sums (stage K tile to SMEM) -> u (block-local!)
// Phase 2: col partials for these 16 rows from the SMEM tile.
// K read ONCE per iteration. No grid sync needed (u dependency is block-local).
__global__ void __launch_bounds__(512) rowcol_kernel() {
    extern __shared__ __align__(16) char dyn[];
    __nv_bfloat16* Kt = (__nv_bfloat16*)dyn;              // [RPB][N] bf16, 128 KB
    float* vs = (float*)(dyn + RPB * N * 2);              // [N] fp32, 16 KB
    float* us = (float*)(dyn + RPB * N * 2 + N * 4);      // [RPB]

    int tid = threadIdx.x;
    int lane = tid & 31, warp = tid >> 5;                 // 16 warps
    uint64_t pol = evict_last_policy();

    // load v to smem (512 threads x 8 floats)
#pragma unroll
    for (int q = 0; q < 2; q++) {
        int f = tid + 512 * q;
        ((float4*)vs)[f] = ((const float4*)g_v)[f];
    }
    __syncthreads();

    // Phase 1: warp w handles row b*16+w
    int row = blockIdx.x * RPB + warp;
    const __nv_bfloat16* Kr = g_Kb + (size_t)row * N;
    __nv_bfloat16* KtRow = Kt + warp * N;
    float s = 0.f;
#pragma unroll
    for (int c = 0; c < 16; c++) {
        int j = c * 256 + lane * 8;
        uint4 dr = ldK16(Kr + j, pol);
        *(uint4*)(KtRow + j) = dr;                        // stage for phase 2
        float2 f0 = __bfloat1622float2(*reinterpret_cast<__nv_bfloat162*>(&dr.x));
        float2 f1 = __bfloat1622float2(*reinterpret_cast<__nv_bfloat162*>(&dr.y));
        float2 f2 = __bfloat1622float2(*reinterpret_cast<__nv_bfloat162*>(&dr.z));
        float2 f3 = __bfloat1622float2(*reinterpret_cast<__nv_bfloat162*>(&dr.w));
        float4 va = *(const float4*)(vs + j);
        float4 vb = *(const float4*)(vs + j + 4);
        s += f0.x * va.x + f0.y * va.y + f1.x * va.z + f1.y * va.w;
        s += f2.x * vb.x + f2.y * vb.y + f3.x * vb.z + f3.y * vb.w;
    }
#pragma unroll
    for (int o = 16; o > 0; o >>= 1) s += __shfl_xor_sync(0xffffffffu, s, o);
    if (lane == 0) {
        float u = (1.0f / N) / (s + 1e-8f);
        us[warp] = u;
        g_u[row] = u;
    }
    __syncthreads();

    // Phase 2: thread t owns 8 cols; sum over the 16 staged rows
    float a0 = 0, a1 = 0, a2 = 0, a3 = 0, a4 = 0, a5 = 0, a6 = 0, a7 = 0;
    int col = tid * 8;
#pragma unroll
    for (int r = 0; r < RPB; r++) {
        float u = us[r];
        uint4 dr = *(const uint4*)(Kt + r * N + col);
        float2 f0 = __bfloat1622float2(*reinterpret_cast<__nv_bfloat162*>(&dr.x));
        float2 f1 = __bfloat1622float2(*reinterpret_cast<__nv_bfloat162*>(&dr.y));
        float2 f2 = __bfloat1622float2(*reinterpret_cast<__nv_bfloat162*>(&dr.z));
        float2 f3 = __bfloat1622float2(*reinterpret_cast<__nv_bfloat162*>(&dr.w));
        a0 += f0.x * u; a1 += f0.y * u; a2 += f1.x * u; a3 += f1.y * u;
        a4 += f2.x * u; a5 += f2.y * u; a6 += f3.x * u; a7 += f3.y * u;
    }
    float* zp = g_zp + (size_t)blockIdx.x * N + col;
    *(float4*)zp       = make_float4(a0, a1, a2, a3);
    *(float4*)(zp + 4) = make_float4(a4, a5, a6, a7);
}

// ---- v = b / (sum over 256 partials + stab) ----
__global__ void fin_kernel() {
    int j = blockIdx.x * 256 + threadIdx.x;
    float s = 0.f;
#pragma unroll 8
    for (int k = 0; k < NBLK; k++) s += g_zp[(size_t)k * N + j];
    g_v[j] = (1.0f / N) / (s + 1e-8f);
}

// ---- coupling = u * exp(-C/8) * v ; vectorized around the +1 misalignment ----
// (OUT_C + row*N + j) and (OUT_P + row*N + j) are both 16B-aligned iff j%4==3.
__global__ void final_kernel(float* __restrict__ out) {
    int row = blockIdx.x, tid = threadIdx.x;
    float u = g_u[row];
    const float* Crow = out + OUT_C + (size_t)row * N;
    float* Prow = out + OUT_P + (size_t)row * N;
    float ls = 0.f;
    // head j=0,1,2 and tail j=4095 by thread 0/1
    if (tid == 0) {
#pragma unroll
        for (int j = 0; j < 3; j++) {
            float C = Crow[j];
            float cp = u * __expf(-0.125f * C) * g_v[j];
            Prow[j] = cp;
            ls += cp * C;
        }
    } else if (tid == 1) {
        float C = Crow[4095];
        float cp = u * __expf(-0.125f * C) * g_v[4095];
        Prow[4095] = cp;
        ls += cp * C;
    }
    // body: 1023 float4 slots, slot q covers j = 3 + 4q  (q = 0..1022)
#pragma unroll 4
    for (int q = tid; q < 1023; q += 256) {
        int j = 3 + 4 * q;
        float4 C4 = __ldcs((const float4*)(Crow + j));
        float4 p;
        p.x = u * __expf(-0.125f * C4.x) * g_v[j];
        p.y = u * __expf(-0.125f * C4.y) * g_v[j + 1];
        p.z = u * __expf(-0.125f * C4.z) * g_v[j + 2];
        p.w = u * __expf(-0.125f * C4.w) * g_v[j + 3];
        __stcs((float4*)(Prow + j), p);
        ls += p.x * C4.x + p.y * C4.y + p.z * C4.z + p.w * C4.w;
    }
    __shared__ float red[256];
    red[tid] = ls;
    __syncthreads();
    for (int o = 128; o > 0; o >>= 1) {
        if (tid < o) red[tid] += red[tid + o];
        __syncthreads();
    }
    if (tid == 0) g_part[row] = red[0];
}

__global__ void loss_kernel(float* __restrict__ out) {
    int tid = threadIdx.x;
    float s = 0.f;
#pragma unroll
    for (int q = 0; q < 16; q++) s += g_part[tid + q * 256];
    __shared__ float red[256];
    red[tid] = s;
    __syncthreads();
    for (int o = 128; o > 0; o >>= 1) {
        if (tid < o) red[tid] += red[tid + o];
        __syncthreads();
    }
    if (tid == 0) out[0] = red[0] * (1.0f / ((float)N * (float)N));
}

extern "C" void kernel_launch(void* const* d_in, const int* in_sizes, int n_in,
                              void* d_out, int out_size) {
    const float* S  = (const float*)d_in[0];
    const float* Tm = (const float*)d_in[1];
    float* out = (float*)d_out;

    __nv_bfloat16 *dSb, *dTb;
    float *dSn, *dTn;
    cudaGetSymbolAddress((void**)&dSb, g_Sb);
    cudaGetSymbolAddress((void**)&dTb, g_Tb);
    cudaGetSymbolAddress((void**)&dSn, g_sn);
    cudaGetSymbolAddress((void**)&dTn, g_tn);

    static bool attr_set = false;
    if (!attr_set) {
        cudaFuncSetAttribute(rowcol_kernel,
                             cudaFuncAttributeMaxDynamicSharedMemorySize, DSMEM);
        attr_set = true;
    }

    init_kernel<<<16, 256>>>();
    cvt_norm_kernel<<<2048, 256>>>(S, dSb, dSn);
    cvt_norm_kernel<<<2048, 256>>>(Tm, dTb, dTn);
    gemm_kernel<<<dim3(32, 32), 256>>>(out);
    for (int it = 0; it < 10; it++) {
        rowcol_kernel<<<NBLK, 512, DSMEM>>>();
        fin_kernel<<<16, 256>>>();
    }
    final_kernel<<<4096, 256>>>(out);
    loss_kernel<<<1, 256>>>(out);
}

// round 10
// speedup vs baseline: 1.2580x; 1.2580x over previous
#include <cuda_runtime.h>
#include <cuda_bf16.h>
#include <cstdint>

#define N 4096
#define D 512
#define NN ((size_t)N * (size_t)N)
#define OUT_P 1
#define OUT_C (1 + 16777216)

// ---- device scratch (no allocations allowed) ----
__device__ __align__(16) __nv_bfloat16 g_Kb[NN];            // 32 MB bf16 K
__device__ __align__(16) __nv_bfloat16 g_KT[NN];            // 32 MB bf16 K^T
__device__ __align__(16) __nv_bfloat16 g_Sb[(size_t)N * D];
__device__ __align__(16) __nv_bfloat16 g_Tb[(size_t)N * D];
__device__ __align__(16) float g_sn[N], g_tn[N];
__device__ __align__(16) float g_u[N], g_v[N];
__device__ __align__(16) float g_part[N];

// ---- L2 evict_last via cache-hint policy ----
__device__ __forceinline__ uint64_t evict_last_policy() {
    uint64_t pol;
    asm("createpolicy.fractional.L2::evict_last.b64 %0, 1.0;" : "=l"(pol));
    return pol;
}
__device__ __forceinline__ uint4 ldK16(const __nv_bfloat16* p, uint64_t pol) {
    uint4 r;
    asm volatile("ld.global.nc.L2::cache_hint.v4.u32 {%0,%1,%2,%3}, [%4], %5;"
                 : "=r"(r.x), "=r"(r.y), "=r"(r.z), "=r"(r.w)
                 : "l"(p), "l"(pol));
    return r;
}
__device__ __forceinline__ void stK4(__nv_bfloat16* p, uint32_t v, uint64_t pol) {
    asm volatile("st.global.L2::cache_hint.u32 [%0], %1, %2;"
                 :: "l"(p), "r"(v), "l"(pol));
}
__device__ __forceinline__ void stK16(__nv_bfloat16* p, uint4 v, uint64_t pol) {
    asm volatile("st.global.L2::cache_hint.v4.u32 [%0], {%1,%2,%3,%4}, %5;"
                 :: "l"(p), "r"(v.x), "r"(v.y), "r"(v.z), "r"(v.w), "l"(pol));
}

// bf16 m16n8k16 mma, fp32 accumulate
__device__ __forceinline__ void mma16(float* c, const uint32_t* a, const uint32_t* b) {
    asm volatile(
        "mma.sync.aligned.m16n8k16.row.col.f32.bf16.bf16.f32 "
        "{%0,%1,%2,%3},{%4,%5,%6,%7},{%8,%9},{%0,%1,%2,%3};"
        : "+f"(c[0]), "+f"(c[1]), "+f"(c[2]), "+f"(c[3])
        : "r"(a[0]), "r"(a[1]), "r"(a[2]), "r"(a[3]), "r"(b[0]), "r"(b[1]));
}

// ---- init: v0 = 1 ----
__global__ void init_kernel() {
    int i = blockIdx.x * blockDim.x + threadIdx.x;
    if (i < N) g_v[i] = 1.0f;
}

// ---- fused convert fp32->bf16 + row sq-norms; one block = 2 rows ----
__global__ void cvt_norm_kernel(const float* __restrict__ X, __nv_bfloat16* __restrict__ Y,
                                float* __restrict__ nrm) {
    __shared__ float ws[8];
    int tid = threadIdx.x;
    size_t base = (size_t)blockIdx.x * 1024 + tid * 4;
    float4 a = *(const float4*)(X + base);
    uint2 o;
    __nv_bfloat162 lo = __floats2bfloat162_rn(a.x, a.y);
    __nv_bfloat162 hi = __floats2bfloat162_rn(a.z, a.w);
    o.x = *(uint32_t*)&lo;
    o.y = *(uint32_t*)&hi;
    *(uint2*)(Y + base) = o;
    float s = a.x * a.x + a.y * a.y + a.z * a.z + a.w * a.w;
#pragma unroll
    for (int of = 16; of > 0; of >>= 1) s += __shfl_xor_sync(0xffffffffu, s, of);
    if ((tid & 31) == 0) ws[tid >> 5] = s;
    __syncthreads();
    if (tid == 0)   nrm[blockIdx.x * 2]     = ws[0] + ws[1] + ws[2] + ws[3];
    if (tid == 128) nrm[blockIdx.x * 2 + 1] = ws[4] + ws[5] + ws[6] + ws[7];
}

// ---- bf16 tensor-core GEMM (proven R7 mainloop) + K / K^T / C epilogue ----
// SMEM: mainloop A/B double buffers (40960 B) reused as the K^T staging tile
// ktbuf[128][136] bf16 (34816 B) in the epilogue.
__global__ void __launch_bounds__(256) gemm_kernel(float* __restrict__ out) {
    __shared__ __align__(16) char smem_all[2 * 128 * 80 * 2];
    char (*As)[128 * 80] = (char(*)[128 * 80])smem_all;
    char (*Bs)[128 * 80] = (char(*)[128 * 80])(smem_all + 2 * 128 * 80);
    const int tid  = threadIdx.x;
    const int lane = tid & 31, warp = tid >> 5;
    const int wm = warp & 1, wn = warp >> 1;
    const int quad = lane >> 2, tb = (lane & 3) * 4;
    const int bi = blockIdx.y, bj = blockIdx.x;

    float acc[4][4][4];
#pragma unroll
    for (int a = 0; a < 4; a++)
#pragma unroll
        for (int b = 0; b < 4; b++)
#pragma unroll
            for (int r = 0; r < 4; r++) acc[a][b][r] = 0.f;

    const __nv_bfloat16* Sb = g_Sb + (size_t)bi * 128 * D;
    const __nv_bfloat16* Tb = g_Tb + (size_t)bj * 128 * D;

    auto load_chunk = [&](int kc, int buf) {
#pragma unroll
        for (int q = 0; q < 2; q++) {
            int f = tid + 256 * q;
            int r = f >> 2, seg = f & 3;
            const __nv_bfloat16* sa = Sb + (size_t)r * D + kc + seg * 8;
            const __nv_bfloat16* sb = Tb + (size_t)r * D + kc + seg * 8;
            uint32_t da = (uint32_t)__cvta_generic_to_shared(&As[buf][r * 80 + seg * 16]);
            uint32_t db = (uint32_t)__cvta_generic_to_shared(&Bs[buf][r * 80 + seg * 16]);
            asm volatile("cp.async.cg.shared.global [%0], [%1], 16;\n\t"
                         "cp.async.cg.shared.global [%2], [%3], 16;"
                         :: "r"(da), "l"(sa), "r"(db), "l"(sb));
        }
        asm volatile("cp.async.commit_group;");
    };

    load_chunk(0, 0);
    for (int c = 0; c < 16; c++) {
        if (c + 1 < 16) {
            load_chunk((c + 1) * 32, (c + 1) & 1);
            asm volatile("cp.async.wait_group 1;");
        } else {
            asm volatile("cp.async.wait_group 0;");
        }
        __syncthreads();
        const char* Ab = As[c & 1];
        const char* Bb = Bs[c & 1];
#pragma unroll
        for (int s = 0; s < 2; s++) {
            const int kb = s * 32 + tb;
            uint32_t aF[4][4], bF[4][2];
#pragma unroll
            for (int mi = 0; mi < 4; mi++) {
                int row = wm * 64 + mi * 16 + quad;
                aF[mi][0] = *(const uint32_t*)(Ab + row * 80 + kb);
                aF[mi][1] = *(const uint32_t*)(Ab + (row + 8) * 80 + kb);
                aF[mi][2] = *(const uint32_t*)(Ab + row * 80 + kb + 16);
                aF[mi][3] = *(const uint32_t*)(Ab + (row + 8) * 80 + kb + 16);
            }
#pragma unroll
            for (int ni = 0; ni < 4; ni++) {
                int nr = wn * 32 + ni * 8 + quad;
                bF[ni][0] = *(const uint32_t*)(Bb + nr * 80 + kb);
                bF[ni][1] = *(const uint32_t*)(Bb + nr * 80 + kb + 16);
            }
#pragma unroll
            for (int mi = 0; mi < 4; mi++)
#pragma unroll
                for (int ni = 0; ni < 4; ni++) mma16(acc[mi][ni], aF[mi], bF[ni]);
        }
        __syncthreads();
    }
    __syncthreads();   // mainloop buffers dead; reuse as ktbuf

    __nv_bfloat16* ktbuf = (__nv_bfloat16*)smem_all;   // [128][136]
    uint64_t pol = evict_last_policy();
    float* outC = out + OUT_C;
#pragma unroll
    for (int mi = 0; mi < 4; mi++) {
#pragma unroll
        for (int ni = 0; ni < 4; ni++) {
            int rl0 = wm * 64 + mi * 16 + quad;
            int cl  = wn * 32 + ni * 8 + (lane & 3) * 2;
            int row0 = bi * 128 + rl0;
            int col  = bj * 128 + cl;
#pragma unroll
            for (int h = 0; h < 2; h++) {
                int rr = row0 + h * 8, rl = rl0 + h * 8;
                float d0 = acc[mi][ni][2 * h], d1 = acc[mi][ni][2 * h + 1];
                float sn = g_sn[rr];
                float c0 = sqrtf(fmaxf(sn + g_tn[col]     - 2.f * d0, 0.f));
                float c1 = sqrtf(fmaxf(sn + g_tn[col + 1] - 2.f * d1, 0.f));
                __stcs(&outC[(size_t)rr * N + col],     c0);
                __stcs(&outC[(size_t)rr * N + col + 1], c1);
                __nv_bfloat162 kk = __floats2bfloat162_rn(__expf(-0.125f * c0),
                                                          __expf(-0.125f * c1));
                stK4(&g_Kb[(size_t)rr * N + col], *(uint32_t*)&kk, pol);
                ktbuf[cl * 136 + rl]       = kk.x;   // transposed staging
                ktbuf[(cl + 1) * 136 + rl] = kk.y;
            }
        }
    }
    __syncthreads();
    // coalesced K^T writes: row j of tile -> g_KT[(bj*128+j)*N + bi*128 ..]
#pragma unroll
    for (int q = 0; q < 8; q++) {
        int idx = tid + 256 * q;            // 0..2047
        int j = idx >> 4, seg = idx & 15;
        uint4 v = *(const uint4*)&ktbuf[j * 136 + seg * 8];
        stK16(&g_KT[(size_t)(bj * 128 + j) * N + bi * 128 + seg * 8], v, pol);
    }
}

// ---- generic scaling pass: o[r] = (1/N) / (sum_j M[r][j] * x[j] + stab) ----
// half-row per warp; 1024 blocks x 8 warps (4 rows/block).
__global__ void row_kernel(const __nv_bfloat16* __restrict__ M,
                           const float* __restrict__ xin,
                           float* __restrict__ xout) {
    __shared__ float vs[N];
    __shared__ float ps[8];
    int tid = threadIdx.x;
#pragma unroll
    for (int q = 0; q < 4; q++) {
        int f = tid + 256 * q;
        ((float4*)vs)[f] = ((const float4*)xin)[f];
    }
    __syncthreads();
    uint64_t pol = evict_last_policy();
    int lane = tid & 31, warp = tid >> 5;
    int row  = blockIdx.x * 4 + (warp >> 1);
    int half = warp & 1;
    const __nv_bfloat16* Kr = M + (size_t)row * N + half * 2048;
    const float* vh = vs + half * 2048;
    float s = 0.f;
#pragma unroll
    for (int c = 0; c < 8; c++) {
        int j = c * 256 + lane * 8;
        uint4 dr = ldK16(Kr + j, pol);
        float2 f0 = __bfloat1622float2(*reinterpret_cast<__nv_bfloat162*>(&dr.x));
        float2 f1 = __bfloat1622float2(*reinterpret_cast<__nv_bfloat162*>(&dr.y));
        float2 f2 = __bfloat1622float2(*reinterpret_cast<__nv_bfloat162*>(&dr.z));
        float2 f3 = __bfloat1622float2(*reinterpret_cast<__nv_bfloat162*>(&dr.w));
        float4 va = *(const float4*)(vh + j);
        float4 vb = *(const float4*)(vh + j + 4);
        s += f0.x * va.x + f0.y * va.y + f1.x * va.z + f1.y * va.w;
        s += f2.x * vb.x + f2.y * vb.y + f3.x * vb.z + f3.y * vb.w;
    }
#pragma unroll
    for (int o = 16; o > 0; o >>= 1) s += __shfl_xor_sync(0xffffffffu, s, o);
    if (lane == 0) ps[warp] = s;
    __syncthreads();
    if (tid < 4)
        xout[blockIdx.x * 4 + tid] = (1.0f / N) / (ps[2 * tid] + ps[2 * tid + 1] + 1e-8f);
}

// ---- coupling = u * exp(-C/8) * v ; vectorized around the +1 misalignment ----
__global__ void final_kernel(float* __restrict__ out) {
    int row = blockIdx.x, tid = threadIdx.x;
    float u = g_u[row];
    const float* Crow = out + OUT_C + (size_t)row * N;
    float* Prow = out + OUT_P + (size_t)row * N;
    float ls = 0.f;
    if (tid == 0) {
#pragma unroll
        for (int j = 0; j < 3; j++) {
            float C = Crow[j];
            float cp = u * __expf(-0.125f * C) * g_v[j];
            Prow[j] = cp;
            ls += cp * C;
        }
    } else if (tid == 1) {
        float C = Crow[4095];
        float cp = u * __expf(-0.125f * C) * g_v[4095];
        Prow[4095] = cp;
        ls += cp * C;
    }
#pragma unroll 4
    for (int q = tid; q < 1023; q += 256) {
        int j = 3 + 4 * q;
        float4 C4 = __ldcs((const float4*)(Crow + j));
        float4 p;
        p.x = u * __expf(-0.125f * C4.x) * g_v[j];
        p.y = u * __expf(-0.125f * C4.y) * g_v[j + 1];
        p.z = u * __expf(-0.125f * C4.z) * g_v[j + 2];
        p.w = u * __expf(-0.125f * C4.w) * g_v[j + 3];
        __stcs((float4*)(Prow + j), p);
        ls += p.x * C4.x + p.y * C4.y + p.z * C4.z + p.w * C4.w;
    }
    __shared__ float red[256];
    red[tid] = ls;
    __syncthreads();
    for (int o = 128; o > 0; o >>= 1) {
        if (tid < o) red[tid] += red[tid + o];
        __syncthreads();
    }
    if (tid == 0) g_part[row] = red[0];
}

__global__ void loss_kernel(float* __restrict__ out) {
    int tid = threadIdx.x;
    float s = 0.f;
#pragma unroll
    for (int q = 0; q < 16; q++) s += g_part[tid + q * 256];
    __shared__ float red[256];
    red[tid] = s;
    __syncthreads();
    for (int o = 128; o > 0; o >>= 1) {
        if (tid < o) red[tid] += red[tid + o];
        __syncthreads();
    }
    if (tid == 0) out[0] = red[0] * (1.0f / ((float)N * (float)N));
}

extern "C" void kernel_launch(void* const* d_in, const int* in_sizes, int n_in,
                              void* d_out, int out_size) {
    const float* S  = (const float*)d_in[0];
    const float* Tm = (const float*)d_in[1];
    float* out = (float*)d_out;

    __nv_bfloat16 *dSb, *dTb, *dK, *dKT;
    float *dSn, *dTn, *dU, *dV;
    cudaGetSymbolAddress((void**)&dSb, g_Sb);
    cudaGetSymbolAddress((void**)&dTb, g_Tb);
    cudaGetSymbolAddress((void**)&dK,  g_Kb);
    cudaGetSymbolAddress((void**)&dKT, g_KT);
    cudaGetSymbolAddress((void**)&dSn, g_sn);
    cudaGetSymbolAddress((void**)&dTn, g_tn);
    cudaGetSymbolAddress((void**)&dU,  g_u);
    cudaGetSymbolAddress((void**)&dV,  g_v);

    init_kernel<<<16, 256>>>();
    cvt_norm_kernel<<<2048, 256>>>(S, dSb, dSn);
    cvt_norm_kernel<<<2048, 256>>>(Tm, dTb, dTn);
    gemm_kernel<<<dim3(32, 32), 256>>>(out);
    for (int it = 0; it < 10; it++) {
        row_kernel<<<1024, 256>>>(dK,  dV, dU);   // u = a/(K v)
        row_kernel<<<1024, 256>>>(dKT, dU, dV);   // v = b/(K^T u)
    }
    final_kernel<<<4096, 256>>>(out);
    loss_kernel<<<1, 256>>>(out);
}